// round 15
// baseline (speedup 1.0000x reference)
#include <cuda_runtime.h>
#include <cstdint>
#include <math.h>

#define NROWS   131072
#define DDIM    128
#define KCODES  1024
#define BM      128         // rows per CTA (stage 1)
#define NC      128         // codes per chunk (stage 1)
#define NCHUNKS (KCODES / NC)
#define PITCHX  132         // Xs pitch in uint32 (33 uint4)
#define PITCHE  64          // Es pitch in uint32 (pairs per d-row)
#define TAU1    2.0f        // bf16 score-margin escalation (13 sigma of model)
#define TAU2    2e-3f       // fp32 dist-margin escalation (validated r9-11)
#define ETP     133         // stage-2 code tile pitch (5 mod 32 -> conflict-free)

// ---- device scratch -------------------------------------------------------
__device__ float g_ET[KCODES * DDIM];   // [K][D] row-major (bitwise copies of E)
__device__ float g_see[KCODES];         // ||e_k||^2 (fp32)
__device__ int   g_cnt;                 // stage-2 row count
__device__ int   g_rows[NROWS];
__device__ int   g_cnt2;                // stage-3 row count
__device__ int   g_rows2[NROWS];

// ---- helpers (standard PTX only) ------------------------------------------
__device__ __forceinline__ unsigned short f2bf(float v) {
    unsigned short h;
    asm("cvt.rn.bf16.f32 %0, %1;" : "=h"(h) : "f"(v));
    return h;
}
__device__ __forceinline__ uint32_t hfma2(uint32_t a, uint32_t b, uint32_t c) {
    uint32_t d;
    asm("fma.rn.bf16x2 %0, %1, %2, %3;" : "=r"(d) : "r"(a), "r"(b), "r"(c));
    return d;
}

// ---------------------------------------------------------------------------
__global__ void vq_prep_kernel(const float* __restrict__ E) {
    int tid    = blockIdx.x * blockDim.x + threadIdx.x;
    int stride = gridDim.x * blockDim.x;
    if (tid == 0) { g_cnt = 0; g_cnt2 = 0; }   // reset per replay (prep first)

    for (int i = tid; i < KCODES * DDIM; i += stride) {
        int d = i / KCODES;
        int k = i - d * KCODES;
        g_ET[k * DDIM + d] = E[i];
    }
    for (int k = tid; k < KCODES; k += stride) {
        float s = 0.f;
        for (int d = 0; d < DDIM; d++) {
            float v = E[d * KCODES + k];
            s = __fmaf_rn(v, v, s);
        }
        g_see[k] = s;
    }
}

// ---------------------------------------------------------------------------
// Stage 1: bf16x2 (HFMA2) tile GEMM with segmented fp32 widening.
// score = see - 2*x.e. 256 threads as 16x16 (ty rows, tx codes), 8 rows x
// 8 codes per thread. Codes packed 2-per-register (low = even code).
// ---------------------------------------------------------------------------
__global__ void __launch_bounds__(256, 1)
vq_main_kernel(const float* __restrict__ X,
               const float* __restrict__ E,
               float* __restrict__ out) {
    extern __shared__ uint32_t smem[];
    uint32_t* Xs    = smem;                      // [DDIM][PITCHX] bcast bf16x2
    uint32_t* Es    = Xs + DDIM * PITCHX;        // [DDIM][PITCHE] code pairs
    float*    see_s = (float*)(Es + DDIM * PITCHE);  // [NC]
    float*    sb1   = see_s + NC;                // [BM]
    float*    sb2   = sb1 + BM;                  // [BM]
    int*      sid   = (int*)(sb2 + BM);          // [BM]
    int*      bidx_s = sid + BM;                 // [BM]

    const int tid = threadIdx.x;
    const int tx  = tid & 15;
    const int ty  = tid >> 4;
    const size_t base = (size_t)blockIdx.x * BM;

    // Xs fill: coalesced global read, bf16 broadcast-pair store.
    for (int i = tid; i < BM * DDIM; i += 256) {
        int m = i >> 7, d = i & 127;
        unsigned short h = f2bf(X[(base + m) * DDIM + d]);
        Xs[d * PITCHX + m] = (uint32_t)h * 0x10001u;
    }

    float bestd[8], secd[8];
    int   bidx[8];
    #pragma unroll
    for (int i = 0; i < 8; i++) { bestd[i] = INFINITY; secd[i] = INFINITY; bidx[i] = 0; }

    const float4* E4   = (const float4*)E;
    const uint4*  Xs4  = (const uint4*)Xs;
    const uint2*  Es2  = (const uint2*)Es;

    #pragma unroll 1
    for (int chunk = 0; chunk < NCHUNKS; chunk++) {
        __syncthreads();   // Xs ready (c=0); prev chunk's Es reads done (c>0)

        // Es fill: E is d-major -> float4 = 4 consecutive codes. Pack low=even.
        for (int i = tid; i < DDIM * (NC / 4); i += 256) {
            int d = i >> 5, q = i & 31;
            float4 v = E4[d * (KCODES / 4) + chunk * (NC / 4) + q];
            uint2 pr;
            pr.x = (uint32_t)f2bf(v.x) | ((uint32_t)f2bf(v.y) << 16);
            pr.y = (uint32_t)f2bf(v.z) | ((uint32_t)f2bf(v.w) << 16);
            *(uint2*)&Es[d * PITCHE + q * 2] = pr;
        }
        if (tid < NC) see_s[tid] = g_see[chunk * NC + tid];
        __syncthreads();

        float facc[8][8];
        #pragma unroll
        for (int i = 0; i < 8; i++)
            #pragma unroll
            for (int j = 0; j < 8; j++) facc[i][j] = 0.f;

        #pragma unroll 1
        for (int seg = 0; seg < DDIM / 16; seg++) {
            uint32_t acc[8][4];
            #pragma unroll
            for (int i = 0; i < 8; i++)
                #pragma unroll
                for (int p = 0; p < 4; p++) acc[i][p] = 0u;

            #pragma unroll
            for (int dd = 0; dd < 16; dd++) {
                const int d = seg * 16 + dd;
                uint4 a0 = Xs4[d * (PITCHX / 4) + ty];        // rows ty*4..+3
                uint4 a1 = Xs4[d * (PITCHX / 4) + 16 + ty];   // rows 64+ty*4..
                uint2 b0 = Es2[d * (PITCHE / 2) + tx];        // codes tx*4..+3
                uint2 b1 = Es2[d * (PITCHE / 2) + 16 + tx];   // codes 64+tx*4..
                uint32_t a[8] = {a0.x, a0.y, a0.z, a0.w, a1.x, a1.y, a1.z, a1.w};
                uint32_t bp[4] = {b0.x, b0.y, b1.x, b1.y};
                #pragma unroll
                for (int i = 0; i < 8; i++)
                    #pragma unroll
                    for (int p = 0; p < 4; p++)
                        acc[i][p] = hfma2(a[i], bp[p], acc[i][p]);
            }
            // widen bf16x2 partials into fp32 accumulators (shift = exact).
            #pragma unroll
            for (int i = 0; i < 8; i++)
                #pragma unroll
                for (int p = 0; p < 4; p++) {
                    facc[i][2 * p]     += __uint_as_float(acc[i][p] << 16);
                    facc[i][2 * p + 1] += __uint_as_float(acc[i][p] & 0xFFFF0000u);
                }
        }

        // Epilogue: score = see - 2*xe; ascending code order -> '<' keeps
        // lowest index within a lane.
        #pragma unroll
        for (int p = 0; p < 4; p++) {
            const int kl = (p < 2) ? (tx * 4 + 2 * p) : (64 + tx * 4 + 2 * (p - 2));
            const float se0 = see_s[kl], se1 = see_s[kl + 1];
            const int   kg  = chunk * NC + kl;
            #pragma unroll
            for (int i = 0; i < 8; i++) {
                float s0 = __fmaf_rn(-2.0f, facc[i][2 * p], se0);
                float s1 = __fmaf_rn(-2.0f, facc[i][2 * p + 1], se1);
                if (s0 < bestd[i]) { secd[i] = bestd[i]; bestd[i] = s0; bidx[i] = kg; }
                else if (s0 < secd[i]) secd[i] = s0;
                if (s1 < bestd[i]) { secd[i] = bestd[i]; bestd[i] = s1; bidx[i] = kg + 1; }
                else if (s1 < secd[i]) secd[i] = s1;
            }
        }
    }

    // Cross-lane top-2 over the 16 tx lanes of each row; flag near-ties.
    #pragma unroll
    for (int i = 0; i < 8; i++) {
        float b1 = bestd[i], b2 = secd[i];
        int   id = bidx[i];
        #pragma unroll
        for (int off = 1; off < 16; off <<= 1) {
            float b1o = __shfl_xor_sync(0xffffffffu, b1, off);
            float b2o = __shfl_xor_sync(0xffffffffu, b2, off);
            int   ido = __shfl_xor_sync(0xffffffffu, id, off);
            float nb2 = fminf(fmaxf(b1, b1o), fminf(b2, b2o));
            if (b1o < b1 || (b1o == b1 && ido < id)) { b1 = b1o; id = ido; }
            b2 = nb2;
        }
        if (tx == 0) {
            int m = (i < 4) ? (ty * 4 + i) : (64 + ty * 4 + (i - 4));
            bidx_s[m] = id;
            if (b2 - b1 < TAU1) {
                int pos = atomicAdd(&g_cnt, 1);
                g_rows[pos] = (int)(base + m);
            }
        }
    }
    __syncthreads();

    // Gather winners (flagged rows overwritten by later stages).
    float4*       out4 = (float4*)out;
    const float4* ET4  = (const float4*)g_ET;
    for (int i = tid; i < BM * (DDIM / 4); i += 256) {
        int m = i >> 5, v = i & 31;
        out4[(base + m) * 32 + v] = ET4[(size_t)bidx_s[m] * 32 + v];
    }
}

// ---------------------------------------------------------------------------
// Stage 2: fp32 full rescan of flagged rows, 32 rows per block with the
// codebook staged through smem tiles (kills the per-row L2 re-read).
// dist = sum (x-e)^2. Escalates margin < TAU2 to fp64 stage 3.
// ---------------------------------------------------------------------------
__global__ void __launch_bounds__(128, 2)
vq_stage2_kernel(const float* __restrict__ X, float* __restrict__ out) {
    __shared__ float xs[32 * DDIM];       // 32 flagged rows
    __shared__ float et[128 * ETP];       // code tile (pitch 133)
    __shared__ int   rows_s[32];

    const int t    = threadIdx.x;
    const int w    = t >> 5;
    const int lane = t & 31;
    const int cnt  = g_cnt;
    const float4* ET4 = (const float4*)g_ET;

    for (int t0 = blockIdx.x * 32; t0 < cnt; t0 += gridDim.x * 32) {
        __syncthreads();   // protect xs/rows_s from previous iteration's readers
        if (t < 32) {
            int idx = t0 + t;
            rows_s[t] = g_rows[idx < cnt ? idx : cnt - 1];
        }
        __syncthreads();
        for (int i = t; i < 32 * DDIM; i += 128) {
            int j = i >> 7, d = i & 127;
            xs[j * DDIM + d] = X[(size_t)rows_s[j] * DDIM + d];
        }

        // Per-warp: 8 rows; per lane: 4 codes per tile, ascending order.
        float b1[8], b2[8];
        int   bi[8];
        #pragma unroll
        for (int j = 0; j < 8; j++) { b1[j] = INFINITY; b2[j] = INFINITY; bi[j] = 0; }

        for (int ct = 0; ct < KCODES / 128; ct++) {
            __syncthreads();   // xs ready (ct=0); prev tile reads done (ct>0)
            for (int i = t; i < 128 * 32; i += 128) {
                int k = i >> 5, v = i & 31;
                float4 q = ET4[(size_t)(ct * 128 + k) * 32 + v];
                float* dst = &et[k * ETP + v * 4];
                dst[0] = q.x; dst[1] = q.y; dst[2] = q.z; dst[3] = q.w;
            }
            __syncthreads();

            #pragma unroll 1
            for (int jj = 0; jj < 8; jj++) {
                const float* xr = &xs[(w * 8 + jj) * DDIM];
                #pragma unroll
                for (int c = 0; c < 4; c++) {
                    const int k = c * 32 + lane;
                    const float* er = &et[k * ETP];
                    float s = 0.f;
                    #pragma unroll 8
                    for (int d = 0; d < DDIM; d++) {
                        float diff = xr[d] - er[d];
                        s = __fmaf_rn(diff, diff, s);
                    }
                    const int kg = ct * 128 + k;
                    if (s < b1[jj])      { b2[jj] = b1[jj]; b1[jj] = s; bi[jj] = kg; }
                    else if (s < b2[jj]) { b2[jj] = s; }
                }
            }
        }

        // Warp-reduce each row's top-2; write winner + maybe flag for fp64.
        #pragma unroll 1
        for (int jj = 0; jj < 8; jj++) {
            float v1 = b1[jj], v2 = b2[jj];
            int   vi = bi[jj];
            #pragma unroll
            for (int off = 1; off < 32; off <<= 1) {
                float o1 = __shfl_xor_sync(0xffffffffu, v1, off);
                float o2 = __shfl_xor_sync(0xffffffffu, v2, off);
                int   oi = __shfl_xor_sync(0xffffffffu, vi, off);
                float n2 = fminf(fmaxf(v1, o1), fminf(v2, o2));
                if (o1 < v1 || (o1 == v1 && oi < vi)) { v1 = o1; vi = oi; }
                v2 = n2;
            }
            const int gidx = t0 + w * 8 + jj;
            if (gidx < cnt) {
                const int row  = rows_s[w * 8 + jj];
                const int widx = __shfl_sync(0xffffffffu, vi, 0);
                if (lane == 0 && (v2 - v1 < TAU2)) {
                    int pos = atomicAdd(&g_cnt2, 1);
                    g_rows2[pos] = row;
                }
                ((float4*)out)[(size_t)row * 32 + lane] = ET4[(size_t)widx * 32 + lane];
            }
        }
    }
}

// ---------------------------------------------------------------------------
// Stage 3: fp64 exact argmin for still-ambiguous rows (tiny count).
// ---------------------------------------------------------------------------
__global__ void __launch_bounds__(128, 4)
vq_stage3_kernel(const float* __restrict__ X, float* __restrict__ out) {
    __shared__ float  xsr[DDIM];
    __shared__ double rd[128];
    __shared__ int    ri[128];
    __shared__ int    wsh;

    const int t = threadIdx.x;
    const int cnt = g_cnt2;

    for (int r = blockIdx.x; r < cnt; r += gridDim.x) {
        const int row = g_rows2[r];
        xsr[t] = X[(size_t)row * DDIM + t];
        __syncthreads();

        double bd = INFINITY;
        int    bi = 0;
        #pragma unroll 1
        for (int c = 0; c < KCODES / 128; c++) {
            int k = t + 128 * c;
            const float* e = &g_ET[k * DDIM];
            double s = 0.0;
            #pragma unroll 8
            for (int d = 0; d < DDIM; d++) {
                double diff = (double)xsr[d] - (double)e[d];
                s = fma(diff, diff, s);
            }
            if (s < bd || (s == bd && k < bi)) { bd = s; bi = k; }
        }
        rd[t] = bd; ri[t] = bi;
        __syncthreads();

        for (int off = 64; off > 0; off >>= 1) {
            if (t < off) {
                double od = rd[t + off]; int oi = ri[t + off];
                if (od < rd[t] || (od == rd[t] && oi < ri[t])) { rd[t] = od; ri[t] = oi; }
            }
            __syncthreads();
        }
        if (t == 0) wsh = ri[0];
        __syncthreads();
        out[(size_t)row * DDIM + t] = g_ET[wsh * DDIM + t];
        __syncthreads();
    }
}

// ---------------------------------------------------------------------------
extern "C" void kernel_launch(void* const* d_in, const int* in_sizes, int n_in,
                              void* d_out, int out_size) {
    const float* X   = (const float*)d_in[0];   // [131072,128]
    const float* E   = (const float*)d_in[1];   // [128,1024]
    float*       out = (float*)d_out;

    vq_prep_kernel<<<64, 256>>>(E);

    const int smem_bytes = (DDIM * PITCHX + DDIM * PITCHE) * 4
                         + (NC + 2 * BM) * 4 + 2 * BM * 4;   // ~103 KB
    cudaFuncSetAttribute(vq_main_kernel,
                         cudaFuncAttributeMaxDynamicSharedMemorySize, smem_bytes);
    vq_main_kernel<<<NROWS / BM, 256, smem_bytes>>>(X, E, out);

    vq_stage2_kernel<<<512, 128>>>(X, out);
    vq_stage3_kernel<<<256, 128>>>(X, out);
}

// round 17
// speedup vs baseline: 1.4667x; 1.4667x over previous
#include <cuda_runtime.h>
#include <cuda_fp16.h>
#include <cstdint>
#include <string.h>
#include <math.h>

#define NROWS   131072
#define DDIM    128
#define KCODES  1024
#define BM      128         // rows per CTA (stage 1)
#define NC      128         // codes per chunk (stage 1)
#define NCHUNKS (KCODES / NC)
#define PITCHX  132         // Xs pitch in uint32 (33 uint4)
#define PITCHE  64          // Es pitch in uint32 (pairs per d-row)
#define SEG     32          // d-steps per fp16 accumulation segment
#define TAU1    0.6f        // fp16 score-margin escalation (~12 sigma)
#define TAU2    2e-3f       // fp32 dist-margin -> inline fp64 arbitration
#define ETP     133         // stage-2 code tile pitch (conflict-free)

// ---- device scratch -------------------------------------------------------
__device__ float g_ET[KCODES * DDIM];   // [K][D] row-major (bitwise copies of E)
__device__ float g_see[KCODES];         // ||e_k||^2 (fp32)
__device__ int   g_cnt;                 // stage-2 row count
__device__ int   g_rows[NROWS];

// ---- bit-reinterpret helpers (no such intrinsics in cuda_fp16.h) ----------
__device__ __forceinline__ uint32_t h2_to_u32(__half2 h) {
    uint32_t u; memcpy(&u, &h, 4); return u;
}
__device__ __forceinline__ __half2 u32_to_h2(uint32_t u) {
    __half2 h; memcpy(&h, &u, 4); return h;
}

// ---------------------------------------------------------------------------
__global__ void vq_prep_kernel(const float* __restrict__ E) {
    int tid    = blockIdx.x * blockDim.x + threadIdx.x;
    int stride = gridDim.x * blockDim.x;
    if (tid == 0) g_cnt = 0;                   // reset per replay (prep first)

    for (int i = tid; i < KCODES * DDIM; i += stride) {
        int d = i / KCODES;
        int k = i - d * KCODES;
        g_ET[k * DDIM + d] = E[i];
    }
    for (int k = tid; k < KCODES; k += stride) {
        float s = 0.f;
        for (int d = 0; d < DDIM; d++) {
            float v = E[d * KCODES + k];
            s = __fmaf_rn(v, v, s);
        }
        g_see[k] = s;
    }
}

// ---------------------------------------------------------------------------
// Stage 1: fp16x2 (native HFMA2) tile GEMM, fp32-widened every SEG d-steps.
// score = see - 2*x.e. 256 threads as 16x16 (ty rows, tx codes), 8 rows x
// 8 codes per thread. Codes packed 2-per-register (low = even code).
// ---------------------------------------------------------------------------
__global__ void __launch_bounds__(256, 1)
vq_main_kernel(const float* __restrict__ X,
               const float* __restrict__ E,
               float* __restrict__ out) {
    extern __shared__ uint32_t smem[];
    uint32_t* Xs    = smem;                      // [DDIM][PITCHX] bcast half2
    uint32_t* Es    = Xs + DDIM * PITCHX;        // [DDIM][PITCHE] code pairs
    float*    see_s = (float*)(Es + DDIM * PITCHE);  // [NC]
    float*    sb1   = see_s + NC;                // [BM]
    float*    sb2   = sb1 + BM;                  // [BM]
    int*      sid   = (int*)(sb2 + BM);          // [BM]
    int*      bidx_s = sid + BM;                 // [BM]

    const int tid = threadIdx.x;
    const int tx  = tid & 15;
    const int ty  = tid >> 4;
    const size_t base = (size_t)blockIdx.x * BM;

    // Xs fill: coalesced global read, fp16 broadcast-pair store.
    for (int i = tid; i < BM * DDIM; i += 256) {
        int m = i >> 7, d = i & 127;
        unsigned short h = __half_as_ushort(__float2half_rn(X[(base + m) * DDIM + d]));
        Xs[d * PITCHX + m] = (uint32_t)h * 0x10001u;
    }

    float bestd[8], secd[8];
    int   bidx[8];
    #pragma unroll
    for (int i = 0; i < 8; i++) { bestd[i] = INFINITY; secd[i] = INFINITY; bidx[i] = 0; }

    const float4* E4   = (const float4*)E;
    const uint4*  Xs4  = (const uint4*)Xs;
    const uint2*  Es2  = (const uint2*)Es;

    #pragma unroll 1
    for (int chunk = 0; chunk < NCHUNKS; chunk++) {
        __syncthreads();   // Xs ready (c=0); prev chunk's Es reads done (c>0)

        // Es fill: E is d-major -> float4 = 4 consecutive codes. Pack low=even.
        for (int i = tid; i < DDIM * (NC / 4); i += 256) {
            int d = i >> 5, q = i & 31;
            float4 v = E4[d * (KCODES / 4) + chunk * (NC / 4) + q];
            uint2 pr;
            pr.x = h2_to_u32(__floats2half2_rn(v.x, v.y));
            pr.y = h2_to_u32(__floats2half2_rn(v.z, v.w));
            *(uint2*)&Es[d * PITCHE + q * 2] = pr;
        }
        if (tid < NC) see_s[tid] = g_see[chunk * NC + tid];
        __syncthreads();

        float facc[8][8];
        #pragma unroll
        for (int i = 0; i < 8; i++)
            #pragma unroll
            for (int j = 0; j < 8; j++) facc[i][j] = 0.f;

        #pragma unroll 1
        for (int seg = 0; seg < DDIM / SEG; seg++) {
            __half2 acc[8][4];
            #pragma unroll
            for (int i = 0; i < 8; i++)
                #pragma unroll
                for (int p = 0; p < 4; p++) acc[i][p] = __floats2half2_rn(0.f, 0.f);

            #pragma unroll
            for (int dd = 0; dd < SEG; dd++) {
                const int d = seg * SEG + dd;
                uint4 a0 = Xs4[d * (PITCHX / 4) + ty];        // rows ty*4..+3
                uint4 a1 = Xs4[d * (PITCHX / 4) + 16 + ty];   // rows 64+ty*4..
                uint2 b0 = Es2[d * (PITCHE / 2) + tx];        // codes tx*4..+3
                uint2 b1 = Es2[d * (PITCHE / 2) + 16 + tx];   // codes 64+tx*4..
                uint32_t a[8] = {a0.x, a0.y, a0.z, a0.w, a1.x, a1.y, a1.z, a1.w};
                uint32_t bp[4] = {b0.x, b0.y, b1.x, b1.y};
                #pragma unroll
                for (int i = 0; i < 8; i++)
                    #pragma unroll
                    for (int p = 0; p < 4; p++)
                        acc[i][p] = __hfma2(u32_to_h2(a[i]),
                                            u32_to_h2(bp[p]), acc[i][p]);
            }
            // widen fp16 partials into fp32 accumulators.
            #pragma unroll
            for (int i = 0; i < 8; i++)
                #pragma unroll
                for (int p = 0; p < 4; p++) {
                    facc[i][2 * p]     += __low2float(acc[i][p]);
                    facc[i][2 * p + 1] += __high2float(acc[i][p]);
                }
        }

        // Epilogue: score = see - 2*xe; ascending code order -> '<' keeps
        // lowest index within a lane.
        #pragma unroll
        for (int p = 0; p < 4; p++) {
            const int kl = (p < 2) ? (tx * 4 + 2 * p) : (64 + tx * 4 + 2 * (p - 2));
            const float se0 = see_s[kl], se1 = see_s[kl + 1];
            const int   kg  = chunk * NC + kl;
            #pragma unroll
            for (int i = 0; i < 8; i++) {
                float s0 = __fmaf_rn(-2.0f, facc[i][2 * p], se0);
                float s1 = __fmaf_rn(-2.0f, facc[i][2 * p + 1], se1);
                if (s0 < bestd[i]) { secd[i] = bestd[i]; bestd[i] = s0; bidx[i] = kg; }
                else if (s0 < secd[i]) secd[i] = s0;
                if (s1 < bestd[i]) { secd[i] = bestd[i]; bestd[i] = s1; bidx[i] = kg + 1; }
                else if (s1 < secd[i]) secd[i] = s1;
            }
        }
    }

    // Cross-lane top-2 over the 16 tx lanes of each row; flag near-ties.
    #pragma unroll
    for (int i = 0; i < 8; i++) {
        float b1 = bestd[i], b2 = secd[i];
        int   id = bidx[i];
        #pragma unroll
        for (int off = 1; off < 16; off <<= 1) {
            float b1o = __shfl_xor_sync(0xffffffffu, b1, off);
            float b2o = __shfl_xor_sync(0xffffffffu, b2, off);
            int   ido = __shfl_xor_sync(0xffffffffu, id, off);
            float nb2 = fminf(fmaxf(b1, b1o), fminf(b2, b2o));
            if (b1o < b1 || (b1o == b1 && ido < id)) { b1 = b1o; id = ido; }
            b2 = nb2;
        }
        if (tx == 0) {
            int m = (i < 4) ? (ty * 4 + i) : (64 + ty * 4 + (i - 4));
            bidx_s[m] = id;
            if (b2 - b1 < TAU1) {
                int pos = atomicAdd(&g_cnt, 1);
                g_rows[pos] = (int)(base + m);
            }
        }
    }
    __syncthreads();

    // Gather winners (flagged rows overwritten by stage 2).
    float4*       out4 = (float4*)out;
    const float4* ET4  = (const float4*)g_ET;
    for (int i = tid; i < BM * (DDIM / 4); i += 256) {
        int m = i >> 5, v = i & 31;
        out4[(base + m) * 32 + v] = ET4[(size_t)bidx_s[m] * 32 + v];
    }
}

// ---------------------------------------------------------------------------
// Stage 2: fp32 full rescan of flagged rows (smem-tiled codebook), tracking
// top-2 values AND indices; near-ties arbitrated inline by fp64 rescore of
// just the two candidate codes.
// ---------------------------------------------------------------------------
__global__ void __launch_bounds__(128, 2)
vq_stage2_kernel(const float* __restrict__ X, float* __restrict__ out) {
    __shared__ float xs[32 * DDIM];       // 32 flagged rows
    __shared__ float et[128 * ETP];       // code tile (pitch 133)
    __shared__ int   rows_s[32];

    const int t    = threadIdx.x;
    const int w    = t >> 5;
    const int lane = t & 31;
    const int cnt  = g_cnt;
    const float4* ET4 = (const float4*)g_ET;

    for (int t0 = blockIdx.x * 32; t0 < cnt; t0 += gridDim.x * 32) {
        __syncthreads();   // protect xs/rows_s from previous iteration's readers
        if (t < 32) {
            int idx = t0 + t;
            rows_s[t] = g_rows[idx < cnt ? idx : cnt - 1];
        }
        __syncthreads();
        for (int i = t; i < 32 * DDIM; i += 128) {
            int j = i >> 7, d = i & 127;
            xs[j * DDIM + d] = X[(size_t)rows_s[j] * DDIM + d];
        }

        float b1[8], b2[8];
        int   i1[8], i2[8];
        #pragma unroll
        for (int j = 0; j < 8; j++) { b1[j] = INFINITY; b2[j] = INFINITY; i1[j] = 0; i2[j] = 0; }

        for (int ct = 0; ct < KCODES / 128; ct++) {
            __syncthreads();   // xs ready (ct=0); prev tile reads done (ct>0)
            for (int i = t; i < 128 * 32; i += 128) {
                int k = i >> 5, v = i & 31;
                float4 q = ET4[(size_t)(ct * 128 + k) * 32 + v];
                float* dst = &et[k * ETP + v * 4];
                dst[0] = q.x; dst[1] = q.y; dst[2] = q.z; dst[3] = q.w;
            }
            __syncthreads();

            #pragma unroll 1
            for (int jj = 0; jj < 8; jj++) {
                const float* xr = &xs[(w * 8 + jj) * DDIM];
                #pragma unroll
                for (int c = 0; c < 4; c++) {
                    const int k = c * 32 + lane;
                    const float* er = &et[k * ETP];
                    float s = 0.f;
                    #pragma unroll 8
                    for (int d = 0; d < DDIM; d++) {
                        float diff = xr[d] - er[d];
                        s = __fmaf_rn(diff, diff, s);
                    }
                    const int kg = ct * 128 + k;
                    if (s < b1[jj])      { b2[jj] = b1[jj]; i2[jj] = i1[jj];
                                           b1[jj] = s;      i1[jj] = kg; }
                    else if (s < b2[jj]) { b2[jj] = s;      i2[jj] = kg; }
                }
            }
        }

        // Per-row: warp-reduce top-2 (values+indices), then decide / arbitrate.
        #pragma unroll 1
        for (int jj = 0; jj < 8; jj++) {
            float v1 = b1[jj], v2 = b2[jj];
            int   j1 = i1[jj], j2 = i2[jj];
            #pragma unroll
            for (int off = 1; off < 32; off <<= 1) {
                float o1 = __shfl_xor_sync(0xffffffffu, v1, off);
                float o2 = __shfl_xor_sync(0xffffffffu, v2, off);
                int   p1 = __shfl_xor_sync(0xffffffffu, j1, off);
                int   p2 = __shfl_xor_sync(0xffffffffu, j2, off);
                float l1; int li1;           // loser of the best-comparison
                if (o1 < v1 || (o1 == v1 && p1 < j1)) {
                    l1 = v1; li1 = j1; v1 = o1; j1 = p1;
                } else { l1 = o1; li1 = p1; }
                // second = min(loser, v2, o2)
                float n2 = l1; int nj2 = li1;
                if (v2 < n2) { n2 = v2; nj2 = j2; }
                if (o2 < n2) { n2 = o2; nj2 = p2; }
                v2 = n2; j2 = nj2;
            }

            const int gidx = t0 + w * 8 + jj;
            if (gidx < cnt) {
                const int row = rows_s[w * 8 + jj];
                int c1 = __shfl_sync(0xffffffffu, j1, 0);
                int c2 = __shfl_sync(0xffffffffu, j2, 0);
                float m1 = __shfl_sync(0xffffffffu, v1, 0);
                float m2 = __shfl_sync(0xffffffffu, v2, 0);
                int widx = c1;
                if (m2 - m1 < TAU2) {
                    // fp64 arbitration of the two candidates (warp-parallel).
                    const float* xr = &xs[(w * 8 + jj) * DDIM];
                    const float* e1 = &g_ET[(size_t)c1 * DDIM];
                    const float* e2 = &g_ET[(size_t)c2 * DDIM];
                    double s1 = 0.0, s2 = 0.0;
                    #pragma unroll
                    for (int dd = 0; dd < 4; dd++) {
                        int d = lane * 4 + dd;
                        double xv = (double)xr[d];
                        double d1 = xv - (double)e1[d];
                        double d2 = xv - (double)e2[d];
                        s1 = fma(d1, d1, s1);
                        s2 = fma(d2, d2, s2);
                    }
                    #pragma unroll
                    for (int off = 1; off < 32; off <<= 1) {
                        s1 += __shfl_xor_sync(0xffffffffu, s1, off);
                        s2 += __shfl_xor_sync(0xffffffffu, s2, off);
                    }
                    widx = (s1 < s2) ? c1
                         : (s2 < s1) ? c2
                         : (c1 < c2 ? c1 : c2);
                    widx = __shfl_sync(0xffffffffu, widx, 0);
                }
                ((float4*)out)[(size_t)row * 32 + lane] = ET4[(size_t)widx * 32 + lane];
            }
        }
    }
}

// ---------------------------------------------------------------------------
extern "C" void kernel_launch(void* const* d_in, const int* in_sizes, int n_in,
                              void* d_out, int out_size) {
    const float* X   = (const float*)d_in[0];   // [131072,128]
    const float* E   = (const float*)d_in[1];   // [128,1024]
    float*       out = (float*)d_out;

    vq_prep_kernel<<<64, 256>>>(E);

    const int smem_bytes = (DDIM * PITCHX + DDIM * PITCHE) * 4
                         + (NC + 2 * BM) * 4 + 2 * BM * 4;   // ~103 KB
    cudaFuncSetAttribute(vq_main_kernel,
                         cudaFuncAttributeMaxDynamicSharedMemorySize, smem_bytes);
    vq_main_kernel<<<NROWS / BM, 256, smem_bytes>>>(X, E, out);

    vq_stage2_kernel<<<512, 128>>>(X, out);
}